// round 1
// baseline (speedup 1.0000x reference)
#include <cuda_runtime.h>
#include <math.h>

// Problem constants
#define NB     8
#define SEQ    512
#define NHEADS 8
#define HD     64
#define DQ     1024            // qdim*embed = vdim*embed
#define MTOK   4096            // NB*SEQ rows of the flattened GEMMs
#define SCALE  0.044194173824159216f  // 1/sqrt(512)

// Scratch (device globals; no allocation allowed)
__device__ float g_q [MTOK * DQ];
__device__ float g_k [MTOK * DQ];
__device__ float g_v [MTOK * DQ];
__device__ float g_ao[MTOK * DQ];

// ---------------------------------------------------------------------------
// SGEMM: C[4096][1024] = A[4096][1024] @ W[1024][1024]^T + bias[1024]
// 64x64 block tile, BK=32, 256 threads, 4x4 microtile.
// ---------------------------------------------------------------------------
__global__ __launch_bounds__(256) void sgemm_bias(
    const float* __restrict__ A, const float* __restrict__ W,
    const float* __restrict__ bias, float* __restrict__ C)
{
    const int K = DQ;
    __shared__ float As[32][68];   // As[kk][i]
    __shared__ float Bs[32][68];   // Bs[kk][j]
    const int tid = threadIdx.x;
    const int ty = tid >> 4, tx = tid & 15;
    const int m0 = blockIdx.y * 64, n0 = blockIdx.x * 64;
    float acc[4][4] = {};

    for (int k0 = 0; k0 < K; k0 += 32) {
        #pragma unroll
        for (int idx = tid; idx < 2048; idx += 256) {
            int i = idx >> 5, kk = idx & 31;
            As[kk][i] = A[(m0 + i) * K + k0 + kk];
            Bs[kk][i] = W[(n0 + i) * K + k0 + kk];
        }
        __syncthreads();
        #pragma unroll
        for (int kk = 0; kk < 32; kk++) {
            float4 av = *(const float4*)&As[kk][ty * 4];
            float4 bv = *(const float4*)&Bs[kk][tx * 4];
            float a4[4] = {av.x, av.y, av.z, av.w};
            float b4[4] = {bv.x, bv.y, bv.z, bv.w};
            #pragma unroll
            for (int ia = 0; ia < 4; ia++)
                #pragma unroll
                for (int ib = 0; ib < 4; ib++)
                    acc[ia][ib] = fmaf(a4[ia], b4[ib], acc[ia][ib]);
        }
        __syncthreads();
    }
    #pragma unroll
    for (int ia = 0; ia < 4; ia++) {
        int row = m0 + ty * 4 + ia;
        #pragma unroll
        for (int ib = 0; ib < 4; ib++) {
            int col = n0 + tx * 4 + ib;
            C[row * DQ + col] = acc[ia][ib] + bias[col];
        }
    }
}

// ---------------------------------------------------------------------------
// Fused flash attention per (n, h):
//   S = Q(1024x64) K^T, mask, scale, online softmax over 1024 cols, O = P V.
// Block: 64 query rows of one (n,h); loops over 32-column K/V tiles.
// Row index r = ql*2 + x; col index c = kl*2 + y  (matches reference reshape).
// ---------------------------------------------------------------------------
__global__ __launch_bounds__(256) void attn_kernel(const int* __restrict__ mask)
{
    const int nh = blockIdx.y;            // 0..63
    const int n = nh >> 3, h = nh & 7;
    const int bx = blockIdx.x;            // row-tile 0..15
    const int tid = threadIdx.x;

    __shared__ float Qs[64][65];          // [row][d]
    __shared__ float Kt[64][36];          // [d][col]      (transposed K tile)
    __shared__ float Vs[32][68];          // [col][d]
    __shared__ float Ss[64][36];          // scores then probs
    __shared__ float m_s[64], l_s[64], a_s[64];
    __shared__ int   msk[32][17];         // [ql_local][kl_local]

    // Load Q tile (64 rows x 64 dims)
    for (int idx = tid; idx < 64 * 64; idx += 256) {
        int i = idx >> 6, d = idx & 63;
        int r = bx * 64 + i;
        int ql = r >> 1, x = r & 1;
        Qs[i][d] = g_q[(n * SEQ + ql) * DQ + x * 512 + h * HD + d];
    }
    if (tid < 64) { m_s[tid] = -INFINITY; l_s[tid] = 0.f; }
    __syncthreads();

    float o[4][4] = {};
    const int ty  = tid >> 4, tx  = tid & 15;  // GEMM2 map: rows ty*4.., dims tx*4..
    const int ty2 = tid >> 3, tx2 = tid & 7;   // GEMM1 map: rows ty2*2.., cols tx2*4..

    for (int t = 0; t < 32; t++) {
        // Load K (transposed) and V tiles; 32 cols x 64 dims
        for (int idx = tid; idx < 32 * 64; idx += 256) {
            int j = idx >> 6, d = idx & 63;
            int c = t * 32 + j;
            int kl = c >> 1, y = c & 1;
            int g = (n * SEQ + kl) * DQ + y * 512 + h * HD + d;
            Kt[d][j] = g_k[g];
            Vs[j][d] = g_v[g];
        }
        // Mask tile: 32 ql-rows x 16 kl-cols
        for (int idx = tid; idx < 512; idx += 256) {
            int qlr = idx >> 4, klr = idx & 15;
            msk[qlr][klr] = mask[(n * SEQ + (bx * 32 + qlr)) * SEQ + t * 16 + klr];
        }
        __syncthreads();

        // GEMM1: S(64x32) = Q K^T
        {
            float s[2][4] = {};
            const int i0 = ty2 * 2;
            #pragma unroll
            for (int d = 0; d < 64; d++) {
                float q0 = Qs[i0][d], q1 = Qs[i0 + 1][d];
                float4 kv = *(const float4*)&Kt[d][tx2 * 4];
                float k4[4] = {kv.x, kv.y, kv.z, kv.w};
                #pragma unroll
                for (int b = 0; b < 4; b++) {
                    s[0][b] = fmaf(q0, k4[b], s[0][b]);
                    s[1][b] = fmaf(q1, k4[b], s[1][b]);
                }
            }
            #pragma unroll
            for (int a = 0; a < 2; a++) {
                int i = i0 + a;
                #pragma unroll
                for (int b = 0; b < 4; b++) {
                    int j = tx2 * 4 + b;
                    // reference: energy = where(mask==0, -1e20, energy); then /sqrt(512)
                    Ss[i][j] = (msk[i >> 1][j >> 1] != 0) ? s[a][b] * SCALE
                                                          : -4.4194e18f;
                }
            }
        }
        __syncthreads();

        // Online softmax row update (64 rows, 1 thread each)
        if (tid < 64) {
            const int r = tid;
            float mo = m_s[r];
            float mx = mo;
            #pragma unroll
            for (int j = 0; j < 32; j++) mx = fmaxf(mx, Ss[r][j]);
            float alpha = __expf(mo - mx);
            float sum = 0.f;
            #pragma unroll
            for (int j = 0; j < 32; j++) {
                float p = __expf(Ss[r][j] - mx);
                Ss[r][j] = p;
                sum += p;
            }
            l_s[r] = l_s[r] * alpha + sum;
            m_s[r] = mx;
            a_s[r] = alpha;
        }
        __syncthreads();

        // GEMM2: O(64x64) = O*alpha + P(64x32) V(32x64)
        #pragma unroll
        for (int a = 0; a < 4; a++) {
            float al = a_s[ty * 4 + a];
            #pragma unroll
            for (int b = 0; b < 4; b++) o[a][b] *= al;
        }
        #pragma unroll
        for (int j = 0; j < 32; j++) {
            float4 vv = *(const float4*)&Vs[j][tx * 4];
            float v4[4] = {vv.x, vv.y, vv.z, vv.w};
            float p[4];
            #pragma unroll
            for (int a = 0; a < 4; a++) p[a] = Ss[ty * 4 + a][j];
            #pragma unroll
            for (int a = 0; a < 4; a++)
                #pragma unroll
                for (int b = 0; b < 4; b++)
                    o[a][b] = fmaf(p[a], v4[b], o[a][b]);
        }
        __syncthreads();
    }

    // Normalize and store to attention-output scratch in (n, ql, x*512 + h*64 + d) layout
    #pragma unroll
    for (int a = 0; a < 4; a++) {
        int i = ty * 4 + a;
        int r = bx * 64 + i;
        int ql = r >> 1, x = r & 1;
        float inv = 1.f / l_s[i];
        #pragma unroll
        for (int b = 0; b < 4; b++) {
            int d = tx * 4 + b;
            g_ao[(n * SEQ + ql) * DQ + x * 512 + h * HD + d] = o[a][b] * inv;
        }
    }
}

// ---------------------------------------------------------------------------
extern "C" void kernel_launch(void* const* d_in, const int* in_sizes, int n_in,
                              void* d_out, int out_size)
{
    const float* query = (const float*)d_in[0];
    const float* key   = (const float*)d_in[1];
    const float* value = (const float*)d_in[2];
    const int*   mask  = (const int*)  d_in[3];
    const float* Wv    = (const float*)d_in[4];
    const float* bv    = (const float*)d_in[5];
    const float* Wk    = (const float*)d_in[6];
    const float* bk    = (const float*)d_in[7];
    const float* Wq    = (const float*)d_in[8];
    const float* bq    = (const float*)d_in[9];
    const float* Wo    = (const float*)d_in[10];
    const float* bo    = (const float*)d_in[11];
    float* out = (float*)d_out;

    float *pq, *pk, *pv, *pao;
    cudaGetSymbolAddress((void**)&pq,  g_q);
    cudaGetSymbolAddress((void**)&pk,  g_k);
    cudaGetSymbolAddress((void**)&pv,  g_v);
    cudaGetSymbolAddress((void**)&pao, g_ao);

    dim3 gg(16, 64), bb(256);
    sgemm_bias<<<gg, bb>>>(query, Wq, bq, pq);
    sgemm_bias<<<gg, bb>>>(key,   Wk, bk, pk);
    sgemm_bias<<<gg, bb>>>(value, Wv, bv, pv);
    attn_kernel<<<dim3(16, 64), bb>>>(mask);
    sgemm_bias<<<gg, bb>>>(pao, Wo, bo, out);
}

// round 2
// speedup vs baseline: 3.5377x; 3.5377x over previous
#include <cuda_runtime.h>
#include <math.h>

#define NB     8
#define SEQ    512
#define HD     64
#define DQ     1024
#define MTOK   4096
#define SCALE  0.044194173824159216f   // 1/sqrt(512)
#define NEG    -4.4194174e18f          // -1e20 * SCALE (masked energy, pre-scaled)

// Scratch (device globals; no allocation allowed)
__device__ float g_q [MTOK * DQ];
__device__ float g_k [MTOK * DQ];
__device__ float g_v [MTOK * DQ];
__device__ float g_ao[MTOK * DQ];

// ---------------------------------------------------------------------------
// tf32 helpers
// ---------------------------------------------------------------------------
__device__ __forceinline__ unsigned f2tf(float x) {
    unsigned u; asm("cvt.rna.tf32.f32 %0, %1;" : "=r"(u) : "f"(x)); return u;
}
__device__ __forceinline__ void mma_tf32(float* c, const unsigned* a, const unsigned* b) {
    asm volatile(
        "mma.sync.aligned.m16n8k8.row.col.f32.tf32.tf32.f32 "
        "{%0,%1,%2,%3}, {%4,%5,%6,%7}, {%8,%9}, {%0,%1,%2,%3};\n"
        : "+f"(c[0]), "+f"(c[1]), "+f"(c[2]), "+f"(c[3])
        : "r"(a[0]), "r"(a[1]), "r"(a[2]), "r"(a[3]), "r"(b[0]), "r"(b[1]));
}

// ---------------------------------------------------------------------------
// GEMM: C[4096][1024] = A[4096][1024] @ W[1024][1024]^T + bias
// Block 128x128, BK=32, 8 warps (2x4), warp tile 64x32 (4x4 m16n8k8 atoms).
// ---------------------------------------------------------------------------
__global__ __launch_bounds__(256) void gemm_tf32(
    const float* __restrict__ A, const float* __restrict__ W,
    const float* __restrict__ bias, float* __restrict__ C)
{
    __shared__ unsigned As[128 * 36];   // [row][k], stride 36 -> bank 4r+k, CF
    __shared__ unsigned Bs[128 * 36];   // [n][k]
    const int tid = threadIdx.x;
    const int warp = tid >> 5, lane = tid & 31;
    const int gid = lane >> 2, tig = lane & 3;
    const int wm = warp >> 2, wn = warp & 3;
    const int m0 = blockIdx.y * 128, n0 = blockIdx.x * 128;

    float c[4][4][4] = {};

    for (int k0 = 0; k0 < 1024; k0 += 32) {
        #pragma unroll
        for (int u = 0; u < 4; u++) {
            int idx = tid + 256 * u;
            int row = idx >> 3, kk = (idx & 7) * 4;
            float4 av = *(const float4*)&A[(long)(m0 + row) * 1024 + k0 + kk];
            float4 bv = *(const float4*)&W[(long)(n0 + row) * 1024 + k0 + kk];
            *(uint4*)&As[row * 36 + kk] = make_uint4(f2tf(av.x), f2tf(av.y), f2tf(av.z), f2tf(av.w));
            *(uint4*)&Bs[row * 36 + kk] = make_uint4(f2tf(bv.x), f2tf(bv.y), f2tf(bv.z), f2tf(bv.w));
        }
        __syncthreads();
        #pragma unroll
        for (int s = 0; s < 4; s++) {
            const int k8 = s * 8;
            unsigned a[4][4], b[4][2];
            #pragma unroll
            for (int ma = 0; ma < 4; ma++) {
                int r = wm * 64 + ma * 16 + gid;
                a[ma][0] = As[r * 36 + k8 + tig];
                a[ma][1] = As[(r + 8) * 36 + k8 + tig];
                a[ma][2] = As[r * 36 + k8 + tig + 4];
                a[ma][3] = As[(r + 8) * 36 + k8 + tig + 4];
            }
            #pragma unroll
            for (int nb = 0; nb < 4; nb++) {
                int cc = wn * 32 + nb * 8 + gid;
                b[nb][0] = Bs[cc * 36 + k8 + tig];
                b[nb][1] = Bs[cc * 36 + k8 + tig + 4];
            }
            #pragma unroll
            for (int ma = 0; ma < 4; ma++)
                #pragma unroll
                for (int nb = 0; nb < 4; nb++)
                    mma_tf32(c[ma][nb], a[ma], b[nb]);
        }
        __syncthreads();
    }
    #pragma unroll
    for (int ma = 0; ma < 4; ma++) {
        int r = m0 + wm * 64 + ma * 16 + gid;
        #pragma unroll
        for (int nb = 0; nb < 4; nb++) {
            int col = n0 + wn * 32 + nb * 8 + 2 * tig;
            float b0 = bias[col], b1 = bias[col + 1];
            *(float2*)&C[(long)r * 1024 + col]       = make_float2(c[ma][nb][0] + b0, c[ma][nb][1] + b1);
            *(float2*)&C[(long)(r + 8) * 1024 + col] = make_float2(c[ma][nb][2] + b0, c[ma][nb][3] + b1);
        }
    }
}

// ---------------------------------------------------------------------------
// Flash attention with tf32 mma. Block = 128 rows of one (n,h), BC=64 cols.
// Row r = ql*2+x, col c = kl*2+y (reference reshape). 8 warps x 16 rows.
// ---------------------------------------------------------------------------
#define ATTN_SMEM_BYTES ((64*68 + 64*68 + 128*68) * 4 + 64*33*4)

__global__ __launch_bounds__(256) void attn_mma(const int* __restrict__ mask)
{
    extern __shared__ unsigned sm[];
    unsigned* Ks = sm;                    // [c:64][d:68]   B-frag reads CF
    unsigned* Vs = Ks + 64 * 68;          // [c:64][d:68]   B-frag reads 2-way
    unsigned* Ps = Vs + 64 * 68;          // [row:128][68]  Q staging, then P
    int* msk = (int*)(Ps + 128 * 68);     // [ql:64][kl:33]

    const int nh = blockIdx.y, n = nh >> 3, h = nh & 7;
    const int bx = blockIdx.x;
    const int tid = threadIdx.x;
    const int warp = tid >> 5, lane = tid & 31;
    const int gid = lane >> 2, tig = lane & 3;
    const int r0 = warp * 16 + gid, r1 = r0 + 8;

    // Stage Q (pre-scaled) into Ps, then pull fragments into registers.
    #pragma unroll
    for (int u = 0; u < 8; u++) {
        int idx = tid + 256 * u;
        int row = idx >> 4, d = (idx & 15) * 4;
        int rg = bx * 128 + row;
        int ql = rg >> 1, x = rg & 1;
        float4 v = *(const float4*)&g_q[(long)(n * SEQ + ql) * DQ + x * 512 + h * HD + d];
        unsigned* p = &Ps[row * 68 + d];
        p[0] = f2tf(v.x * SCALE); p[1] = f2tf(v.y * SCALE);
        p[2] = f2tf(v.z * SCALE); p[3] = f2tf(v.w * SCALE);
    }
    __syncthreads();
    unsigned q[8][4];
    #pragma unroll
    for (int s = 0; s < 8; s++) {
        q[s][0] = Ps[r0 * 68 + 8 * s + tig];
        q[s][1] = Ps[r1 * 68 + 8 * s + tig];
        q[s][2] = Ps[r0 * 68 + 8 * s + tig + 4];
        q[s][3] = Ps[r1 * 68 + 8 * s + tig + 4];
    }
    __syncthreads();

    float o[8][4] = {};
    float m0 = -INFINITY, m1 = -INFINITY, l0 = 0.f, l1 = 0.f;
    const int qll0 = r0 >> 1, qll1 = qll0 + 4;

    for (int t = 0; t < 16; t++) {
        // Load K, V tiles (64 cols x 64 dims) and mask tile
        #pragma unroll
        for (int u = 0; u < 4; u++) {
            int idx = tid + 256 * u;
            int cc = idx >> 4, d = (idx & 15) * 4;
            int cg = t * 64 + cc;
            int kl = cg >> 1, y = cg & 1;
            long base = (long)(n * SEQ + kl) * DQ + y * 512 + h * HD + d;
            float4 kv = *(const float4*)&g_k[base];
            float4 vv = *(const float4*)&g_v[base];
            *(uint4*)&Ks[cc * 68 + d] = make_uint4(f2tf(kv.x), f2tf(kv.y), f2tf(kv.z), f2tf(kv.w));
            *(uint4*)&Vs[cc * 68 + d] = make_uint4(f2tf(vv.x), f2tf(vv.y), f2tf(vv.z), f2tf(vv.w));
        }
        #pragma unroll
        for (int u = 0; u < 8; u++) {
            int idx = tid + 256 * u;
            int qlr = idx >> 5, klr = idx & 31;
            msk[qlr * 33 + klr] = mask[(long)(n * SEQ + bx * 64 + qlr) * SEQ + t * 32 + klr];
        }
        __syncthreads();

        // S(128x64) = Q K^T
        float s[8][4] = {};
        #pragma unroll
        for (int ks = 0; ks < 8; ks++) {
            #pragma unroll
            for (int j = 0; j < 8; j++) {
                unsigned b[2];
                b[0] = Ks[(8 * j + gid) * 68 + 8 * ks + tig];
                b[1] = Ks[(8 * j + gid) * 68 + 8 * ks + tig + 4];
                mma_tf32(s[j], q[ks], b);
            }
        }

        // Mask + online softmax (rows r0, r1 per thread, replicated x4 in quad)
        float mx0 = m0, mx1 = m1;
        #pragma unroll
        for (int j = 0; j < 8; j++) {
            int klc = 4 * j + tig;
            bool k0m = msk[qll0 * 33 + klc] != 0;
            bool k1m = msk[qll1 * 33 + klc] != 0;
            s[j][0] = k0m ? s[j][0] : NEG;
            s[j][1] = k0m ? s[j][1] : NEG;
            s[j][2] = k1m ? s[j][2] : NEG;
            s[j][3] = k1m ? s[j][3] : NEG;
            mx0 = fmaxf(mx0, fmaxf(s[j][0], s[j][1]));
            mx1 = fmaxf(mx1, fmaxf(s[j][2], s[j][3]));
        }
        mx0 = fmaxf(mx0, __shfl_xor_sync(0xffffffffu, mx0, 1));
        mx0 = fmaxf(mx0, __shfl_xor_sync(0xffffffffu, mx0, 2));
        mx1 = fmaxf(mx1, __shfl_xor_sync(0xffffffffu, mx1, 1));
        mx1 = fmaxf(mx1, __shfl_xor_sync(0xffffffffu, mx1, 2));
        float a0 = __expf(m0 - mx0), a1 = __expf(m1 - mx1);
        float sum0 = 0.f, sum1 = 0.f;
        #pragma unroll
        for (int j = 0; j < 8; j++) {
            float p00 = __expf(s[j][0] - mx0), p01 = __expf(s[j][1] - mx0);
            float p10 = __expf(s[j][2] - mx1), p11 = __expf(s[j][3] - mx1);
            sum0 += p00 + p01; sum1 += p10 + p11;
            *(uint2*)&Ps[r0 * 68 + 8 * j + 2 * tig] = make_uint2(f2tf(p00), f2tf(p01));
            *(uint2*)&Ps[r1 * 68 + 8 * j + 2 * tig] = make_uint2(f2tf(p10), f2tf(p11));
        }
        sum0 += __shfl_xor_sync(0xffffffffu, sum0, 1);
        sum0 += __shfl_xor_sync(0xffffffffu, sum0, 2);
        sum1 += __shfl_xor_sync(0xffffffffu, sum1, 1);
        sum1 += __shfl_xor_sync(0xffffffffu, sum1, 2);
        l0 = l0 * a0 + sum0; l1 = l1 * a1 + sum1;
        m0 = mx0; m1 = mx1;
        #pragma unroll
        for (int j = 0; j < 8; j++) {
            o[j][0] *= a0; o[j][1] *= a0; o[j][2] *= a1; o[j][3] *= a1;
        }

        // O += P V  (P rows are this warp's own rows; no cross-warp dependency)
        #pragma unroll
        for (int ks = 0; ks < 8; ks++) {
            unsigned a[4];
            a[0] = Ps[r0 * 68 + 8 * ks + tig];
            a[1] = Ps[r1 * 68 + 8 * ks + tig];
            a[2] = Ps[r0 * 68 + 8 * ks + tig + 4];
            a[3] = Ps[r1 * 68 + 8 * ks + tig + 4];
            #pragma unroll
            for (int j = 0; j < 8; j++) {
                unsigned b[2];
                b[0] = Vs[(8 * ks + tig) * 68 + 8 * j + gid];
                b[1] = Vs[(8 * ks + tig + 4) * 68 + 8 * j + gid];
                mma_tf32(o[j], a, b);
            }
        }
        __syncthreads();
    }

    // Normalize + store
    float inv0 = 1.f / l0, inv1 = 1.f / l1;
    int rg0 = bx * 128 + r0, rg1 = rg0 + 8;
    int ql0 = rg0 >> 1, x0 = rg0 & 1;
    int ql1 = rg1 >> 1, x1 = rg1 & 1;
    float* out0 = &g_ao[(long)(n * SEQ + ql0) * DQ + x0 * 512 + h * HD];
    float* out1 = &g_ao[(long)(n * SEQ + ql1) * DQ + x1 * 512 + h * HD];
    #pragma unroll
    for (int j = 0; j < 8; j++) {
        *(float2*)&out0[8 * j + 2 * tig] = make_float2(o[j][0] * inv0, o[j][1] * inv0);
        *(float2*)&out1[8 * j + 2 * tig] = make_float2(o[j][2] * inv1, o[j][3] * inv1);
    }
}

// ---------------------------------------------------------------------------
extern "C" void kernel_launch(void* const* d_in, const int* in_sizes, int n_in,
                              void* d_out, int out_size)
{
    const float* query = (const float*)d_in[0];
    const float* key   = (const float*)d_in[1];
    const float* value = (const float*)d_in[2];
    const int*   mask  = (const int*)  d_in[3];
    const float* Wv    = (const float*)d_in[4];
    const float* bv    = (const float*)d_in[5];
    const float* Wk    = (const float*)d_in[6];
    const float* bk    = (const float*)d_in[7];
    const float* Wq    = (const float*)d_in[8];
    const float* bq    = (const float*)d_in[9];
    const float* Wo    = (const float*)d_in[10];
    const float* bo    = (const float*)d_in[11];
    float* out = (float*)d_out;

    float *pq, *pk, *pv, *pao;
    cudaGetSymbolAddress((void**)&pq,  g_q);
    cudaGetSymbolAddress((void**)&pk,  g_k);
    cudaGetSymbolAddress((void**)&pv,  g_v);
    cudaGetSymbolAddress((void**)&pao, g_ao);

    static bool attr_set = false;
    if (!attr_set) {
        cudaFuncSetAttribute(attn_mma, cudaFuncAttributeMaxDynamicSharedMemorySize,
                             ATTN_SMEM_BYTES);
        attr_set = true;
    }

    dim3 gg(8, 32), bb(256);
    gemm_tf32<<<gg, bb>>>(query, Wq, bq, pq);
    gemm_tf32<<<gg, bb>>>(key,   Wk, bk, pk);
    gemm_tf32<<<gg, bb>>>(value, Wv, bv, pv);
    attn_mma<<<dim3(8, 64), bb, ATTN_SMEM_BYTES>>>(mask);
    gemm_tf32<<<gg, bb>>>(pao, Wo, bo, out);
}

// round 5
// speedup vs baseline: 4.2554x; 1.2029x over previous
#include <cuda_runtime.h>
#include <cuda_fp16.h>
#include <math.h>
#include <cstdint>

#define SEQ    512
#define DQ     1024
#define MTOK   4096
#define SCALE  0.044194173824159216f   // 1/sqrt(512)
#define NEG    -4.4194174e18f          // -1e20 * SCALE

// Scratch (device globals; no allocation allowed)
__device__ __half g_q [MTOK * DQ];
__device__ __half g_k [MTOK * DQ];
__device__ __half g_v [MTOK * DQ];
__device__ float  g_ao[MTOK * DQ];

// ---------------------------------------------------------------------------
// helpers
// ---------------------------------------------------------------------------
__device__ __forceinline__ unsigned f2tf(float x) {
    unsigned u; asm("cvt.rna.tf32.f32 %0, %1;" : "=r"(u) : "f"(x)); return u;
}
__device__ __forceinline__ void mma_tf32(float* c, const unsigned* a, const unsigned* b) {
    asm volatile(
        "mma.sync.aligned.m16n8k8.row.col.f32.tf32.tf32.f32 "
        "{%0,%1,%2,%3}, {%4,%5,%6,%7}, {%8,%9}, {%0,%1,%2,%3};\n"
        : "+f"(c[0]), "+f"(c[1]), "+f"(c[2]), "+f"(c[3])
        : "r"(a[0]), "r"(a[1]), "r"(a[2]), "r"(a[3]), "r"(b[0]), "r"(b[1]));
}
__device__ __forceinline__ void mma_f16(float* c, const unsigned* a, const unsigned* b) {
    asm volatile(
        "mma.sync.aligned.m16n8k16.row.col.f32.f16.f16.f32 "
        "{%0,%1,%2,%3}, {%4,%5,%6,%7}, {%8,%9}, {%0,%1,%2,%3};\n"
        : "+f"(c[0]), "+f"(c[1]), "+f"(c[2]), "+f"(c[3])
        : "r"(a[0]), "r"(a[1]), "r"(a[2]), "r"(a[3]), "r"(b[0]), "r"(b[1]));
}
__device__ __forceinline__ uint2 f4_h4(float4 v) {
    __half2 lo = __floats2half2_rn(v.x, v.y);
    __half2 hi = __floats2half2_rn(v.z, v.w);
    uint2 r;
    r.x = *(unsigned*)&lo;
    r.y = *(unsigned*)&hi;
    return r;
}

// ---------------------------------------------------------------------------
// fp16 GEMM body: C[4096][1024] = A[4096][1024] @ W[1024][1024]^T + bias
// Block 128x128, BK=32, 8 warps (2x4), warp tile 64x32 (m16n8k16 atoms).
// Smem stride 20 uints (16 half2 + 4 pad) -> conflict-free fragment LDS.
// ---------------------------------------------------------------------------
template<bool HALF_OUT>
__device__ __forceinline__ void gemm_body(
    const float* __restrict__ A, const float* __restrict__ W,
    const float* __restrict__ bias, void* Cv)
{
    __shared__ unsigned As[128 * 20];   // half2 [row][k2]
    __shared__ unsigned Bs[128 * 20];
    const int tid = threadIdx.x;
    const int warp = tid >> 5, lane = tid & 31;
    const int gid = lane >> 2, tig = lane & 3;
    const int wm = warp >> 2, wn = warp & 3;
    const int m0 = blockIdx.y * 128, n0 = blockIdx.x * 128;

    float c[4][4][4] = {};

    for (int k0 = 0; k0 < 1024; k0 += 32) {
        #pragma unroll
        for (int u = 0; u < 4; u++) {
            int idx = tid + 256 * u;
            int row = idx >> 3, q = idx & 7;
            uint2 av = f4_h4(*(const float4*)&A[(long)(m0 + row) * 1024 + k0 + q * 4]);
            uint2 bv = f4_h4(*(const float4*)&W[(long)(n0 + row) * 1024 + k0 + q * 4]);
            *(uint2*)&As[row * 20 + q * 2] = av;
            *(uint2*)&Bs[row * 20 + q * 2] = bv;
        }
        __syncthreads();
        #pragma unroll
        for (int s = 0; s < 2; s++) {
            const int k2 = s * 8;
            unsigned a[4][4], b[4][2];
            #pragma unroll
            for (int ma = 0; ma < 4; ma++) {
                int r = wm * 64 + ma * 16 + gid;
                a[ma][0] = As[r * 20 + k2 + tig];
                a[ma][1] = As[(r + 8) * 20 + k2 + tig];
                a[ma][2] = As[r * 20 + k2 + tig + 4];
                a[ma][3] = As[(r + 8) * 20 + k2 + tig + 4];
            }
            #pragma unroll
            for (int nb = 0; nb < 4; nb++) {
                int cc = wn * 32 + nb * 8 + gid;
                b[nb][0] = Bs[cc * 20 + k2 + tig];
                b[nb][1] = Bs[cc * 20 + k2 + tig + 4];
            }
            #pragma unroll
            for (int ma = 0; ma < 4; ma++)
                #pragma unroll
                for (int nb = 0; nb < 4; nb++)
                    mma_f16(c[ma][nb], a[ma], b[nb]);
        }
        __syncthreads();
    }

    #pragma unroll
    for (int ma = 0; ma < 4; ma++) {
        int r = m0 + wm * 64 + ma * 16 + gid;
        #pragma unroll
        for (int nb = 0; nb < 4; nb++) {
            int col = n0 + wn * 32 + nb * 8 + 2 * tig;
            float b0 = bias[col], b1 = bias[col + 1];
            if (HALF_OUT) {
                __half* C = (__half*)Cv;
                __half2 v0 = __floats2half2_rn(c[ma][nb][0] + b0, c[ma][nb][1] + b1);
                __half2 v1 = __floats2half2_rn(c[ma][nb][2] + b0, c[ma][nb][3] + b1);
                *(__half2*)&C[(long)r * 1024 + col]       = v0;
                *(__half2*)&C[(long)(r + 8) * 1024 + col] = v1;
            } else {
                float* C = (float*)Cv;
                *(float2*)&C[(long)r * 1024 + col] =
                    make_float2(c[ma][nb][0] + b0, c[ma][nb][1] + b1);
                *(float2*)&C[(long)(r + 8) * 1024 + col] =
                    make_float2(c[ma][nb][2] + b0, c[ma][nb][3] + b1);
            }
        }
    }
}

// Q/K/V projections fused into one launch (gridDim.z selects)
__global__ __launch_bounds__(256) void gemm_qkv(
    const float* __restrict__ q_in, const float* __restrict__ k_in,
    const float* __restrict__ v_in,
    const float* __restrict__ Wq, const float* __restrict__ bq,
    const float* __restrict__ Wk, const float* __restrict__ bk,
    const float* __restrict__ Wv, const float* __restrict__ bv)
{
    const float *A, *W, *b;
    __half* C;
    if (blockIdx.z == 0)      { A = q_in; W = Wq; b = bq; C = g_q; }
    else if (blockIdx.z == 1) { A = k_in; W = Wk; b = bk; C = g_k; }
    else                      { A = v_in; W = Wv; b = bv; C = g_v; }
    gemm_body<true>(A, W, b, C);
}

__global__ __launch_bounds__(256) void gemm_out(
    const float* __restrict__ A, const float* __restrict__ W,
    const float* __restrict__ bias, float* __restrict__ C)
{
    gemm_body<false>(A, W, bias, C);
}

// ---------------------------------------------------------------------------
// Flash attention. S = Q K^T in fp16 mma (m16n8k16), softmax fp32,
// O += P V in tf32 mma (m16n8k8, V upconverted half->tf32 exactly).
// Block = 128 rows of one (n,h), BC=64 cols. Row r = ql*2+x, col c = kl*2+y.
// ---------------------------------------------------------------------------
#define ATTN_SMEM_BYTES ((64*36 + 64*68 + 128*68) * 4 + 64*33*4)

__global__ __launch_bounds__(256, 2) void attn_mma(const int* __restrict__ mask)
{
    extern __shared__ unsigned smA[];
    unsigned* Ks = smA;                   // half2 [c:64][d2:36]
    unsigned* Vs = Ks + 64 * 36;          // tf32  [c:64][d:68]
    unsigned* Ps = Vs + 64 * 68;          // [row:128][68]: Q staging (half2) then P (tf32)
    int* msk = (int*)(Ps + 128 * 68);     // [ql:64][kl:33]

    const int nh = blockIdx.y, n = nh >> 3, h = nh & 7;
    const int bx = blockIdx.x;
    const int tid = threadIdx.x;
    const int warp = tid >> 5, lane = tid & 31;
    const int gid = lane >> 2, tig = lane & 3;
    const int r0 = warp * 16 + gid, r1 = r0 + 8;

    const __half2 sc2 = __floats2half2_rn(SCALE, SCALE);

    // Stage Q (pre-scaled, half2) into Ps: 128 rows x 16 half2-pairs = 2048 items
    #pragma unroll
    for (int u = 0; u < 8; u++) {
        int idx = tid + 256 * u;
        int row = idx >> 4, d = (idx & 15) * 4;
        int rg = bx * 128 + row;
        int ql = rg >> 1, x = rg & 1;
        uint2 v = *(const uint2*)&g_q[(long)(n * SEQ + ql) * DQ + x * 512 + h * 64 + d];
        __half2 h0 = __hmul2(*(__half2*)&v.x, sc2);
        __half2 h1 = __hmul2(*(__half2*)&v.y, sc2);
        Ps[row * 68 + d / 2]     = *(unsigned*)&h0;
        Ps[row * 68 + d / 2 + 1] = *(unsigned*)&h1;
    }
    __syncthreads();
    unsigned q[4][4];
    #pragma unroll
    for (int s = 0; s < 4; s++) {
        q[s][0] = Ps[r0 * 68 + 8 * s + tig];
        q[s][1] = Ps[r1 * 68 + 8 * s + tig];
        q[s][2] = Ps[r0 * 68 + 8 * s + tig + 4];
        q[s][3] = Ps[r1 * 68 + 8 * s + tig + 4];
    }
    __syncthreads();

    float o[8][4] = {};
    float m0 = -INFINITY, m1 = -INFINITY, l0 = 0.f, l1 = 0.f;
    const int qll0 = r0 >> 1, qll1 = qll0 + 4;

    for (int t = 0; t < 16; t++) {
        // Load K (half2), V (tf32) tiles: 64 cols x 64 dims
        #pragma unroll
        for (int u = 0; u < 4; u++) {
            int idx = tid + 256 * u;
            int cc = idx >> 4, d = (idx & 15) * 4;
            int cg = t * 64 + cc;
            int kl = cg >> 1, y = cg & 1;
            long base = (long)(n * SEQ + kl) * DQ + y * 512 + h * 64 + d;
            uint2 kv = *(const uint2*)&g_k[base];
            uint2 vv = *(const uint2*)&g_v[base];
            *(uint2*)&Ks[cc * 36 + d / 2] = kv;
            __half2 v0 = *(__half2*)&vv.x, v1 = *(__half2*)&vv.y;
            *(uint4*)&Vs[cc * 68 + d] = make_uint4(
                f2tf(__low2float(v0)), f2tf(__high2float(v0)),
                f2tf(__low2float(v1)), f2tf(__high2float(v1)));
        }
        #pragma unroll
        for (int u = 0; u < 8; u++) {
            int idx = tid + 256 * u;
            int qlr = idx >> 5, klr = idx & 31;
            msk[qlr * 33 + klr] = mask[(long)(n * SEQ + bx * 64 + qlr) * SEQ + t * 32 + klr];
        }
        __syncthreads();

        // S(128x64) = Q K^T  (fp16, 4 k16-steps)
        float s[8][4] = {};
        #pragma unroll
        for (int ks = 0; ks < 4; ks++) {
            #pragma unroll
            for (int j = 0; j < 8; j++) {
                unsigned b[2];
                b[0] = Ks[(8 * j + gid) * 36 + 8 * ks + tig];
                b[1] = Ks[(8 * j + gid) * 36 + 8 * ks + tig + 4];
                mma_f16(s[j], q[ks], b);
            }
        }

        // Mask + online softmax (rows r0, r1 per thread)
        float mx0 = m0, mx1 = m1;
        #pragma unroll
        for (int j = 0; j < 8; j++) {
            int klc = 4 * j + tig;
            bool k0m = msk[qll0 * 33 + klc] != 0;
            bool k1m = msk[qll1 * 33 + klc] != 0;
            s[j][0] = k0m ? s[j][0] : NEG;
            s[j][1] = k0m ? s[j][1] : NEG;
            s[j][2] = k1m ? s[j][2] : NEG;
            s[j][3] = k1m ? s[j][3] : NEG;
            mx0 = fmaxf(mx0, fmaxf(s[j][0], s[j][1]));
            mx1 = fmaxf(mx1, fmaxf(s[j][2], s[j][3]));
        }
        mx0 = fmaxf(mx0, __shfl_xor_sync(0xffffffffu, mx0, 1));
        mx0 = fmaxf(mx0, __shfl_xor_sync(0xffffffffu, mx0, 2));
        mx1 = fmaxf(mx1, __shfl_xor_sync(0xffffffffu, mx1, 1));
        mx1 = fmaxf(mx1, __shfl_xor_sync(0xffffffffu, mx1, 2));
        float a0 = __expf(m0 - mx0), a1 = __expf(m1 - mx1);
        float sum0 = 0.f, sum1 = 0.f;
        #pragma unroll
        for (int j = 0; j < 8; j++) {
            float p00 = __expf(s[j][0] - mx0), p01 = __expf(s[j][1] - mx0);
            float p10 = __expf(s[j][2] - mx1), p11 = __expf(s[j][3] - mx1);
            sum0 += p00 + p01; sum1 += p10 + p11;
            *(uint2*)&Ps[r0 * 68 + 8 * j + 2 * tig] = make_uint2(f2tf(p00), f2tf(p01));
            *(uint2*)&Ps[r1 * 68 + 8 * j + 2 * tig] = make_uint2(f2tf(p10), f2tf(p11));
        }
        sum0 += __shfl_xor_sync(0xffffffffu, sum0, 1);
        sum0 += __shfl_xor_sync(0xffffffffu, sum0, 2);
        sum1 += __shfl_xor_sync(0xffffffffu, sum1, 1);
        sum1 += __shfl_xor_sync(0xffffffffu, sum1, 2);
        l0 = l0 * a0 + sum0; l1 = l1 * a1 + sum1;
        m0 = mx0; m1 = mx1;
        #pragma unroll
        for (int j = 0; j < 8; j++) {
            o[j][0] *= a0; o[j][1] *= a0; o[j][2] *= a1; o[j][3] *= a1;
        }

        // O += P V  (tf32, P rows are this warp's own rows)
        #pragma unroll
        for (int ks = 0; ks < 8; ks++) {
            unsigned a[4];
            a[0] = Ps[r0 * 68 + 8 * ks + tig];
            a[1] = Ps[r1 * 68 + 8 * ks + tig];
            a[2] = Ps[r0 * 68 + 8 * ks + tig + 4];
            a[3] = Ps[r1 * 68 + 8 * ks + tig + 4];
            #pragma unroll
            for (int j = 0; j < 8; j++) {
                unsigned b[2];
                b[0] = Vs[(8 * ks + tig) * 68 + 8 * j + gid];
                b[1] = Vs[(8 * ks + tig + 4) * 68 + 8 * j + gid];
                mma_tf32(o[j], a, b);
            }
        }
        __syncthreads();
    }

    // Normalize + store (fp32 scratch for the output projection)
    float inv0 = 1.f / l0, inv1 = 1.f / l1;
    int rg0 = bx * 128 + r0, rg1 = rg0 + 8;
    int ql0 = rg0 >> 1, x0 = rg0 & 1;
    int ql1 = rg1 >> 1, x1 = rg1 & 1;
    float* out0 = &g_ao[(long)(n * SEQ + ql0) * DQ + x0 * 512 + h * 64];
    float* out1 = &g_ao[(long)(n * SEQ + ql1) * DQ + x1 * 512 + h * 64];
    #pragma unroll
    for (int j = 0; j < 8; j++) {
        *(float2*)&out0[8 * j + 2 * tig] = make_float2(o[j][0] * inv0, o[j][1] * inv0);
        *(float2*)&out1[8 * j + 2 * tig] = make_float2(o[j][2] * inv1, o[j][3] * inv1);
    }
}

// ---------------------------------------------------------------------------
extern "C" void kernel_launch(void* const* d_in, const int* in_sizes, int n_in,
                              void* d_out, int out_size)
{
    const float* query = (const float*)d_in[0];
    const float* key   = (const float*)d_in[1];
    const float* value = (const float*)d_in[2];
    const int*   mask  = (const int*)  d_in[3];
    const float* Wv    = (const float*)d_in[4];
    const float* bv    = (const float*)d_in[5];
    const float* Wk    = (const float*)d_in[6];
    const float* bk    = (const float*)d_in[7];
    const float* Wq    = (const float*)d_in[8];
    const float* bq    = (const float*)d_in[9];
    const float* Wo    = (const float*)d_in[10];
    const float* bo    = (const float*)d_in[11];
    float* out = (float*)d_out;

    float* pao;
    cudaGetSymbolAddress((void**)&pao, g_ao);

    static bool attr_set = false;
    if (!attr_set) {
        cudaFuncSetAttribute(attn_mma, cudaFuncAttributeMaxDynamicSharedMemorySize,
                             ATTN_SMEM_BYTES);
        attr_set = true;
    }

    dim3 bb(256);
    gemm_qkv<<<dim3(8, 32, 3), bb>>>(query, key, value, Wq, bq, Wk, bk, Wv, bv);
    attn_mma<<<dim3(8, 64), bb, ATTN_SMEM_BYTES>>>(mask);
    gemm_out<<<dim3(8, 32), bb>>>(pao, Wo, bo, out);
}

// round 6
// speedup vs baseline: 6.5459x; 1.5383x over previous
#include <cuda_runtime.h>
#include <cuda_fp16.h>
#include <math.h>
#include <cstdint>

#define SEQ    512
#define DQ     1024
#define MTOK   4096
#define SCALE  0.044194173824159216f   // 1/sqrt(512)
#define NEG    -4.4194174e18f          // -1e20 * SCALE

// Scratch (device globals; no allocation allowed)
__device__ __half g_xq[MTOK * DQ];   // converted inputs
__device__ __half g_xk[MTOK * DQ];
__device__ __half g_xv[MTOK * DQ];
__device__ __half g_wq[DQ * DQ];     // converted weights
__device__ __half g_wk[DQ * DQ];
__device__ __half g_wv[DQ * DQ];
__device__ __half g_wo[DQ * DQ];
__device__ __half g_q [MTOK * DQ];   // projections
__device__ __half g_k [MTOK * DQ];
__device__ __half g_v [MTOK * DQ];
__device__ __half g_ao[MTOK * DQ];   // attention output

// ---------------------------------------------------------------------------
// helpers
// ---------------------------------------------------------------------------
__device__ __forceinline__ void mma_f16(float* c, const unsigned* a, const unsigned* b) {
    asm volatile(
        "mma.sync.aligned.m16n8k16.row.col.f32.f16.f16.f32 "
        "{%0,%1,%2,%3}, {%4,%5,%6,%7}, {%8,%9}, {%0,%1,%2,%3};\n"
        : "+f"(c[0]), "+f"(c[1]), "+f"(c[2]), "+f"(c[3])
        : "r"(a[0]), "r"(a[1]), "r"(a[2]), "r"(a[3]), "r"(b[0]), "r"(b[1]));
}
__device__ __forceinline__ uint32_t smem_u32(const void* p) {
    uint32_t a;
    asm("{ .reg .u64 t; cvta.to.shared.u64 t, %1; cvt.u32.u64 %0, t; }" : "=r"(a) : "l"(p));
    return a;
}
__device__ __forceinline__ void cp16(uint32_t s, const void* g) {
    asm volatile("cp.async.cg.shared.global [%0], [%1], 16;" :: "r"(s), "l"(g));
}
#define CP_COMMIT() asm volatile("cp.async.commit_group;" ::: "memory")
__device__ __forceinline__ unsigned pack_h2(float x, float y) {
    __half2 h = __floats2half2_rn(x, y);
    return *(unsigned*)&h;
}

// ---------------------------------------------------------------------------
// f32 -> f16 conversion of inputs and weights, one pass.
// Flat float4 index space: [0,1M) q, [1M,2M) k, [2M,3M) v,
// then 256K each for Wv, Wk, Wq, Wo.  Total 4M float4s.
// ---------------------------------------------------------------------------
__global__ __launch_bounds__(256) void cvt_kernel(
    const float* __restrict__ q, const float* __restrict__ k, const float* __restrict__ v,
    const float* __restrict__ wv, const float* __restrict__ wk,
    const float* __restrict__ wq, const float* __restrict__ wo)
{
    const long stride = (long)gridDim.x * blockDim.x;
    for (long i = (long)blockIdx.x * blockDim.x + threadIdx.x; i < 4194304; i += stride) {
        const float* src; __half* dst; long off;
        if (i < 3145728) {
            int which = (int)(i >> 20);
            off = i & 1048575;
            src = which == 0 ? q : which == 1 ? k : v;
            dst = which == 0 ? g_xq : which == 1 ? g_xk : g_xv;
        } else {
            long j = i - 3145728;
            int which = (int)(j >> 18);
            off = j & 262143;
            src = which == 0 ? wv : which == 1 ? wk : which == 2 ? wq : wo;
            dst = which == 0 ? g_wv : which == 1 ? g_wk : which == 2 ? g_wq : g_wo;
        }
        float4 val = ((const float4*)src)[off];
        uint2 h;
        h.x = pack_h2(val.x, val.y);
        h.y = pack_h2(val.z, val.w);
        ((uint2*)dst)[off] = h;
    }
}

// ---------------------------------------------------------------------------
// Pipelined fp16 GEMM: C[4096][1024] = A @ W^T + bias.
// 128x128 tile, BK=64, 3-stage cp.async ring, 8 warps (2x4), 64x32 warp tile.
// Smem: per stage A 128x36 uints (32 data + 4 pad), same for B.
// ---------------------------------------------------------------------------
#define GSTG  4608                     // uints per tile stage (128*36)
#define GEMM_SMEM (6 * GSTG * 4)       // 110592 bytes

template<bool HALF_OUT>
__device__ __forceinline__ void gemm_body(
    const __half* __restrict__ A, const __half* __restrict__ W,
    const float* __restrict__ bias, void* Cv)
{
    extern __shared__ __align__(16) unsigned sm[];
    const int tid = threadIdx.x;
    const int warp = tid >> 5, lane = tid & 31;
    const int gid = lane >> 2, tig = lane & 3;
    const int wm = warp >> 2, wn = warp & 3;
    const int m0 = blockIdx.y * 128, n0 = blockIdx.x * 128;
    const uint32_t smb = smem_u32(sm);

    float c[4][4][4] = {};

    auto issue = [&](int stage) {
        const int buf = stage % 3;
        const long k0 = (long)stage * 64;
        const uint32_t ab = smb + buf * (GSTG * 4);
        const uint32_t bb = smb + 3 * (GSTG * 4) + buf * (GSTG * 4);
        #pragma unroll
        for (int u = 0; u < 4; u++) {
            int chunk = tid + 256 * u;
            int row = chunk >> 3, qq = chunk & 7;
            cp16(ab + (row * 36 + qq * 4) * 4, &A[(long)(m0 + row) * 1024 + k0 + qq * 8]);
        }
        #pragma unroll
        for (int u = 0; u < 4; u++) {
            int chunk = tid + 256 * u;
            int row = chunk >> 3, qq = chunk & 7;
            cp16(bb + (row * 36 + qq * 4) * 4, &W[(long)(n0 + row) * 1024 + k0 + qq * 8]);
        }
        CP_COMMIT();
    };

    issue(0);
    issue(1);

    for (int ch = 0; ch < 16; ch++) {
        if (ch < 14) asm volatile("cp.async.wait_group 1;" ::: "memory");
        else         asm volatile("cp.async.wait_group 0;" ::: "memory");
        __syncthreads();
        if (ch + 2 < 16) issue(ch + 2);

        unsigned* Ab = sm + (ch % 3) * GSTG;
        unsigned* Bb = sm + 3 * GSTG + (ch % 3) * GSTG;
        #pragma unroll
        for (int s = 0; s < 4; s++) {
            const int k2 = s * 8;
            unsigned a[4][4], b[4][2];
            #pragma unroll
            for (int ma = 0; ma < 4; ma++) {
                int r = wm * 64 + ma * 16 + gid;
                a[ma][0] = Ab[r * 36 + k2 + tig];
                a[ma][1] = Ab[(r + 8) * 36 + k2 + tig];
                a[ma][2] = Ab[r * 36 + k2 + tig + 4];
                a[ma][3] = Ab[(r + 8) * 36 + k2 + tig + 4];
            }
            #pragma unroll
            for (int nb = 0; nb < 4; nb++) {
                int cc = wn * 32 + nb * 8 + gid;
                b[nb][0] = Bb[cc * 36 + k2 + tig];
                b[nb][1] = Bb[cc * 36 + k2 + tig + 4];
            }
            #pragma unroll
            for (int ma = 0; ma < 4; ma++)
                #pragma unroll
                for (int nb = 0; nb < 4; nb++)
                    mma_f16(c[ma][nb], a[ma], b[nb]);
        }
    }

    #pragma unroll
    for (int ma = 0; ma < 4; ma++) {
        int r = m0 + wm * 64 + ma * 16 + gid;
        #pragma unroll
        for (int nb = 0; nb < 4; nb++) {
            int col = n0 + wn * 32 + nb * 8 + 2 * tig;
            float b0 = bias[col], b1 = bias[col + 1];
            if (HALF_OUT) {
                __half* C = (__half*)Cv;
                __half2 v0 = __floats2half2_rn(c[ma][nb][0] + b0, c[ma][nb][1] + b1);
                __half2 v1 = __floats2half2_rn(c[ma][nb][2] + b0, c[ma][nb][3] + b1);
                *(__half2*)&C[(long)r * 1024 + col]       = v0;
                *(__half2*)&C[(long)(r + 8) * 1024 + col] = v1;
            } else {
                float* C = (float*)Cv;
                *(float2*)&C[(long)r * 1024 + col] =
                    make_float2(c[ma][nb][0] + b0, c[ma][nb][1] + b1);
                *(float2*)&C[(long)(r + 8) * 1024 + col] =
                    make_float2(c[ma][nb][2] + b0, c[ma][nb][3] + b1);
            }
        }
    }
}

__global__ __launch_bounds__(256, 2) void gemm_qkv(
    const float* __restrict__ bq, const float* __restrict__ bk, const float* __restrict__ bv)
{
    if (blockIdx.z == 0)      gemm_body<true>(g_xq, g_wq, bq, g_q);
    else if (blockIdx.z == 1) gemm_body<true>(g_xk, g_wk, bk, g_k);
    else                      gemm_body<true>(g_xv, g_wv, bv, g_v);
}

__global__ __launch_bounds__(256, 2) void gemm_out(
    const float* __restrict__ bo, float* __restrict__ C)
{
    gemm_body<false>(g_ao, g_wo, bo, C);
}

// ---------------------------------------------------------------------------
// Flash attention, all-fp16 mma, register-resident P.
// Block = 128 rows of one (n,h), BC=64 cols. Row r = ql*2+x, col c = kl*2+y.
// ---------------------------------------------------------------------------
#define ATTN_SMEM_BYTES ((64*36 + 32*68 + 128*36 + 64*36) * 4)

__global__ __launch_bounds__(256, 2) void attn_mma(const int* __restrict__ mask)
{
    extern __shared__ unsigned smA[];
    unsigned* Ks = smA;                   // half2 [c:64][36]   (32 data + 4 pad)
    unsigned* Vt = Ks + 64 * 36;          // half2 pairs-along-c [c2:32][68]
    unsigned* Qs = Vt + 32 * 68;          // half2 [row:128][36]
    int* msk = (int*)(Qs + 128 * 36);     // [ql:64][36]

    const int nh = blockIdx.y, n = nh >> 3, h = nh & 7;
    const int bx = blockIdx.x;
    const int tid = threadIdx.x;
    const int warp = tid >> 5, lane = tid & 31;
    const int gid = lane >> 2, tig = lane & 3;
    const int r0 = warp * 16 + gid, r1 = r0 + 8;

    const __half2 sc2 = __floats2half2_rn(SCALE, SCALE);

    // Stage Q (pre-scaled, half2): 128 rows x 16 groups of 4 halves
    #pragma unroll
    for (int u = 0; u < 8; u++) {
        int idx = tid + 256 * u;
        int row = idx >> 4, d = (idx & 15) * 4;
        int rg = bx * 128 + row;
        int ql = rg >> 1, x = rg & 1;
        uint2 v = *(const uint2*)&g_q[(long)(n * SEQ + ql) * DQ + x * 512 + h * 64 + d];
        __half2 h0 = __hmul2(*(__half2*)&v.x, sc2);
        __half2 h1 = __hmul2(*(__half2*)&v.y, sc2);
        Qs[row * 36 + d / 2]     = *(unsigned*)&h0;
        Qs[row * 36 + d / 2 + 1] = *(unsigned*)&h1;
    }
    __syncthreads();
    unsigned q[4][4];
    #pragma unroll
    for (int s = 0; s < 4; s++) {
        q[s][0] = Qs[r0 * 36 + 8 * s + tig];
        q[s][1] = Qs[r1 * 36 + 8 * s + tig];
        q[s][2] = Qs[r0 * 36 + 8 * s + tig + 4];
        q[s][3] = Qs[r1 * 36 + 8 * s + tig + 4];
    }
    __syncthreads();

    float o[8][4] = {};
    float m0 = -INFINITY, m1 = -INFINITY, l0 = 0.f, l1 = 0.f;
    const int qll0 = r0 >> 1, qll1 = qll0 + 4;

    for (int t = 0; t < 16; t++) {
        // K tile: 64 cols x 64 dims (half2, direct)
        #pragma unroll
        for (int u = 0; u < 4; u++) {
            int idx = tid + 256 * u;
            int cc = idx >> 4, d = (idx & 15) * 4;
            int cg = t * 64 + cc;
            int kl = cg >> 1, y = cg & 1;
            uint2 kv = *(const uint2*)&g_k[(long)(n * SEQ + kl) * DQ + y * 512 + h * 64 + d];
            *(uint2*)&Ks[cc * 36 + d / 2] = kv;
        }
        // V tile repacked: Vt[c2][d] = half2{ V[2*c2][d], V[2*c2+1][d] }
        // pair (2c2, 2c2+1) = same kl, y=0/1 -> rows 512 apart
        #pragma unroll
        for (int u = 0; u < 2; u++) {
            int idx = tid + 256 * u;
            int c2 = idx >> 4, d4 = (idx & 15) * 4;
            int kl = t * 32 + c2;
            long base = (long)(n * SEQ + kl) * DQ + h * 64 + d4;
            uint2 lo = *(const uint2*)&g_v[base];          // y=0 (even c)
            uint2 hi = *(const uint2*)&g_v[base + 512];    // y=1 (odd c)
            __half2 l0h = *(__half2*)&lo.x, l1h = *(__half2*)&lo.y;
            __half2 h0h = *(__half2*)&hi.x, h1h = *(__half2*)&hi.y;
            __half2 p0 = __halves2half2(__low2half(l0h),  __low2half(h0h));
            __half2 p1 = __halves2half2(__high2half(l0h), __high2half(h0h));
            __half2 p2 = __halves2half2(__low2half(l1h),  __low2half(h1h));
            __half2 p3 = __halves2half2(__high2half(l1h), __high2half(h1h));
            *(uint4*)&Vt[c2 * 68 + d4] = make_uint4(
                *(unsigned*)&p0, *(unsigned*)&p1, *(unsigned*)&p2, *(unsigned*)&p3);
        }
        // mask tile: 64 ql x 32 kl
        #pragma unroll
        for (int u = 0; u < 8; u++) {
            int idx = tid + 256 * u;
            int qlr = idx >> 5, klr = idx & 31;
            msk[qlr * 36 + klr] = mask[(long)(n * SEQ + bx * 64 + qlr) * SEQ + t * 32 + klr];
        }
        __syncthreads();

        // S(128x64) = Q K^T  (fp16, 4 k16-steps)
        float s[8][4] = {};
        #pragma unroll
        for (int ks = 0; ks < 4; ks++) {
            #pragma unroll
            for (int j = 0; j < 8; j++) {
                unsigned b[2];
                b[0] = Ks[(8 * j + gid) * 36 + 8 * ks + tig];
                b[1] = Ks[(8 * j + gid) * 36 + 8 * ks + tig + 4];
                mma_f16(s[j], q[ks], b);
            }
        }

        // Mask + online softmax (rows r0, r1 per thread)
        float mx0 = m0, mx1 = m1;
        #pragma unroll
        for (int j = 0; j < 8; j++) {
            int klc = 4 * j + tig;
            bool k0m = msk[qll0 * 36 + klc] != 0;
            bool k1m = msk[qll1 * 36 + klc] != 0;
            s[j][0] = k0m ? s[j][0] : NEG;
            s[j][1] = k0m ? s[j][1] : NEG;
            s[j][2] = k1m ? s[j][2] : NEG;
            s[j][3] = k1m ? s[j][3] : NEG;
            mx0 = fmaxf(mx0, fmaxf(s[j][0], s[j][1]));
            mx1 = fmaxf(mx1, fmaxf(s[j][2], s[j][3]));
        }
        mx0 = fmaxf(mx0, __shfl_xor_sync(0xffffffffu, mx0, 1));
        mx0 = fmaxf(mx0, __shfl_xor_sync(0xffffffffu, mx0, 2));
        mx1 = fmaxf(mx1, __shfl_xor_sync(0xffffffffu, mx1, 1));
        mx1 = fmaxf(mx1, __shfl_xor_sync(0xffffffffu, mx1, 2));
        float a0 = __expf(m0 - mx0), a1 = __expf(m1 - mx1);
        float sum0 = 0.f, sum1 = 0.f;
        #pragma unroll
        for (int j = 0; j < 8; j++) {
            s[j][0] = __expf(s[j][0] - mx0);
            s[j][1] = __expf(s[j][1] - mx0);
            s[j][2] = __expf(s[j][2] - mx1);
            s[j][3] = __expf(s[j][3] - mx1);
            sum0 += s[j][0] + s[j][1];
            sum1 += s[j][2] + s[j][3];
        }
        sum0 += __shfl_xor_sync(0xffffffffu, sum0, 1);
        sum0 += __shfl_xor_sync(0xffffffffu, sum0, 2);
        sum1 += __shfl_xor_sync(0xffffffffu, sum1, 1);
        sum1 += __shfl_xor_sync(0xffffffffu, sum1, 2);
        l0 = l0 * a0 + sum0; l1 = l1 * a1 + sum1;
        m0 = mx0; m1 = mx1;
        #pragma unroll
        for (int j = 0; j < 8; j++) {
            o[j][0] *= a0; o[j][1] *= a0; o[j][2] *= a1; o[j][3] *= a1;
        }

        // O += P V (fp16, P fragments built in registers: C-frag layout == A-frag k-pairs)
        #pragma unroll
        for (int ks = 0; ks < 4; ks++) {
            unsigned a[4];
            a[0] = pack_h2(s[2 * ks][0],     s[2 * ks][1]);
            a[1] = pack_h2(s[2 * ks][2],     s[2 * ks][3]);
            a[2] = pack_h2(s[2 * ks + 1][0], s[2 * ks + 1][1]);
            a[3] = pack_h2(s[2 * ks + 1][2], s[2 * ks + 1][3]);
            #pragma unroll
            for (int j = 0; j < 8; j++) {
                unsigned b[2];
                b[0] = Vt[(8 * ks + tig) * 68 + 8 * j + gid];
                b[1] = Vt[(8 * ks + tig + 4) * 68 + 8 * j + gid];
                mma_f16(o[j], a, b);
            }
        }
        __syncthreads();
    }

    // Normalize + store (half, consumed by gemm_out)
    float inv0 = 1.f / l0, inv1 = 1.f / l1;
    int rg0 = bx * 128 + r0, rg1 = rg0 + 8;
    int ql0 = rg0 >> 1, x0 = rg0 & 1;
    int ql1 = rg1 >> 1, x1 = rg1 & 1;
    __half* out0 = &g_ao[(long)(n * SEQ + ql0) * DQ + x0 * 512 + h * 64];
    __half* out1 = &g_ao[(long)(n * SEQ + ql1) * DQ + x1 * 512 + h * 64];
    #pragma unroll
    for (int j = 0; j < 8; j++) {
        *(__half2*)&out0[8 * j + 2 * tig] = __floats2half2_rn(o[j][0] * inv0, o[j][1] * inv0);
        *(__half2*)&out1[8 * j + 2 * tig] = __floats2half2_rn(o[j][2] * inv1, o[j][3] * inv1);
    }
}

// ---------------------------------------------------------------------------
extern "C" void kernel_launch(void* const* d_in, const int* in_sizes, int n_in,
                              void* d_out, int out_size)
{
    const float* query = (const float*)d_in[0];
    const float* key   = (const float*)d_in[1];
    const float* value = (const float*)d_in[2];
    const int*   mask  = (const int*)  d_in[3];
    const float* Wv    = (const float*)d_in[4];
    const float* bv    = (const float*)d_in[5];
    const float* Wk    = (const float*)d_in[6];
    const float* bk    = (const float*)d_in[7];
    const float* Wq    = (const float*)d_in[8];
    const float* bq    = (const float*)d_in[9];
    const float* Wo    = (const float*)d_in[10];
    const float* bo    = (const float*)d_in[11];
    float* out = (float*)d_out;

    static bool attr_set = false;
    if (!attr_set) {
        cudaFuncSetAttribute(attn_mma, cudaFuncAttributeMaxDynamicSharedMemorySize,
                             ATTN_SMEM_BYTES);
        cudaFuncSetAttribute(gemm_qkv, cudaFuncAttributeMaxDynamicSharedMemorySize,
                             GEMM_SMEM);
        cudaFuncSetAttribute(gemm_out, cudaFuncAttributeMaxDynamicSharedMemorySize,
                             GEMM_SMEM);
        attr_set = true;
    }

    dim3 bb(256);
    cvt_kernel<<<2048, bb>>>(query, key, value, Wv, Wk, Wq, Wo);
    gemm_qkv<<<dim3(8, 32, 3), bb, GEMM_SMEM>>>(bq, bk, bv);
    attn_mma<<<dim3(8, 64), bb, ATTN_SMEM_BYTES>>>(mask);
    gemm_out<<<dim3(8, 32), bb, GEMM_SMEM>>>(bo, out);
}